// round 3
// baseline (speedup 1.0000x reference)
#include <cuda_runtime.h>

#define DD 64
#define MAXN 50000
#define MAXE 800000

typedef unsigned long long ull;

// ---------------- scratch (device globals: no allocation allowed) ----------
__device__ __align__(16) float g_esrc[(size_t)MAXN * DD];
__device__ __align__(16) float g_edst[(size_t)MAXN * DD];
__device__ __align__(16) float g_Bh  [(size_t)MAXN * DD];
__device__ __align__(16) float g_xs  [(size_t)MAXN * DD];
__device__ __align__(16) float g_xpre[(size_t)MAXN * DD];
__device__ __align__(16) float g_num [(size_t)MAXN * DD];
__device__ __align__(16) float g_den [(size_t)MAXN * DD];
__device__ __align__(16) float g_m   [(size_t)MAXE * DD];
// [0:64) edge_sum [64:128) edge_sumsq [128:192) node_sum [192:256) node_sumsq
// [256:320) edge_scale [320:384) edge_shift [384:448) node_scale [448:512) node_shift
__device__ __align__(16) float g_stats[512];

__device__ __forceinline__ float sigmoidf_(float x) {
    return __fdividef(1.0f, 1.0f + __expf(-x));
}
__device__ __forceinline__ ull pk(float lo, float hi) {
    ull r; asm("mov.b64 %0, {%1, %2};" : "=l"(r) : "f"(lo), "f"(hi)); return r;
}
__device__ __forceinline__ void upk(ull v, float& lo, float& hi) {
    asm("mov.b64 {%0, %1}, %2;" : "=f"(lo), "=f"(hi) : "l"(v));
}
__device__ __forceinline__ ull fma2(ull a, ull b, ull c) {
    ull d; asm("fma.rn.f32x2 %0, %1, %2, %3;" : "=l"(d) : "l"(a), "l"(b), "l"(c)); return d;
}
// vector reduction: 4 fp32 adds in one L2 op (sm_90+)
__device__ __forceinline__ void red4(float* p, float a, float b, float c, float d) {
    asm volatile("{\n\t.reg .u64 q;\n\tcvta.to.global.u64 q, %0;\n\t"
                 "red.global.add.v4.f32 [q], {%1, %2, %3, %4};\n\t}"
                 :: "l"(p), "f"(a), "f"(b), "f"(c), "f"(d) : "memory");
}

// ---------------- node-side 4 GEMMs (N x 64 @ 64 x 64), FFMA2 ----------------
// 64 rows/block, 256 threads: thread = 4 rows (rg) x 4 cols (cg).
// input tile stored DUPLICATED (float2(v,v)) so LDS.64 yields packed operand.
__global__ __launch_bounds__(256) void node_gemm4(
    const float* __restrict__ nf,
    const float* __restrict__ Wsg, const float* __restrict__ bsg,
    const float* __restrict__ Wdg, const float* __restrict__ bdg,
    const float* __restrict__ Wsu, const float* __restrict__ bsu,
    const float* __restrict__ Wdu, const float* __restrict__ bdu,
    int n)
{
    __shared__ float2 shI2[64 * 64];   // 32 KB duplicated input
    __shared__ float  shW [64 * 64];   // 16 KB weights
    const int tid = threadIdx.x;
    const int tile0 = blockIdx.x * 64;

    for (int i = tid; i < 64 * 16; i += 256) {
        int r = i >> 4, c4 = (i & 15) << 2;
        float4 v = make_float4(0.f, 0.f, 0.f, 0.f);
        int row = tile0 + r;
        if (row < n) v = *reinterpret_cast<const float4*>(nf + (size_t)row * DD + c4);
        shI2[r * 64 + c4 + 0] = make_float2(v.x, v.x);
        shI2[r * 64 + c4 + 1] = make_float2(v.y, v.y);
        shI2[r * 64 + c4 + 2] = make_float2(v.z, v.z);
        shI2[r * 64 + c4 + 3] = make_float2(v.w, v.w);
    }

    const float* Ws[4] = {Wsg, Wdg, Wsu, Wdu};
    const float* bs[4] = {bsg, bdg, bsu, bdu};
    float* outs[4] = {g_esrc, g_edst, g_xs, g_Bh};

    const int cg = tid & 15, rg = tid >> 4;
    const ull* shIu = reinterpret_cast<const ull*>(shI2);
    const ull* shWu = reinterpret_cast<const ull*>(shW);

    #pragma unroll
    for (int p = 0; p < 4; ++p) {
        __syncthreads();
        for (int i = tid; i < 64 * 16; i += 256)
            reinterpret_cast<float4*>(shW)[i] = reinterpret_cast<const float4*>(Ws[p])[i];
        __syncthreads();

        float4 bb = reinterpret_cast<const float4*>(bs[p])[cg];
        ull b01 = pk(bb.x, bb.y), b23 = pk(bb.z, bb.w);
        ull a01[4] = {b01, b01, b01, b01};
        ull a23[4] = {b23, b23, b23, b23};
        #pragma unroll 4
        for (int k = 0; k < 64; k++) {
            ull w01 = shWu[k * 32 + (cg << 1)];
            ull w23 = shWu[k * 32 + (cg << 1) + 1];
            #pragma unroll
            for (int r = 0; r < 4; r++) {
                ull ev = shIu[(rg * 4 + r) * 64 + k];
                a01[r] = fma2(ev, w01, a01[r]);
                a23[r] = fma2(ev, w23, a23[r]);
            }
        }
        float* op = outs[p];
        #pragma unroll
        for (int r = 0; r < 4; r++) {
            int row = tile0 + rg * 4 + r;
            if (row < n) {
                float4 o;
                upk(a01[r], o.x, o.y); upk(a23[r], o.z, o.w);
                *reinterpret_cast<float4*>(op + (size_t)row * DD + (cg << 2)) = o;
            }
        }
    }

    // fused zeroing of num/den for this row tile + stats (block 0)
    float4 z = make_float4(0.f, 0.f, 0.f, 0.f);
    for (int i = tid; i < 64 * 16; i += 256) {
        int r = i >> 4, c4 = (i & 15) << 2;
        int row = tile0 + r;
        if (row < n) {
            *reinterpret_cast<float4*>(g_num + (size_t)row * DD + c4) = z;
            *reinterpret_cast<float4*>(g_den + (size_t)row * DD + c4) = z;
        }
    }
    if (blockIdx.x == 0) g_stats[tid] = 0.f;   // zero sums [0:256)
}

// ---------------- edge pass 1: FFMA2 GEMM + gather + sigma + red.v4 scatter --
// 32 edges/block, 256 threads: thread = 2 rows (rg in [0,16)) x 4 cols (cg).
__global__ __launch_bounds__(256) void edge_pass1(
    const float* __restrict__ ef, const int* __restrict__ eidx,
    const float* __restrict__ Weg, const float* __restrict__ beg,
    int nE)
{
    __shared__ float2 shE2[32 * 64];   // 16 KB duplicated edge tile
    __shared__ float  shW [64 * 64];   // 16 KB weights
    __shared__ int shS[32], shD[32];
    __shared__ float shSum[64], shSq[64];

    const int tid = threadIdx.x;
    const int tile0 = blockIdx.x * 32;

    if (tid < 64) { shSum[tid] = 0.f; shSq[tid] = 0.f; }
    if (tid < 32) {
        int e = tile0 + tid;
        shS[tid] = (e < nE) ? eidx[e] : 0;
        shD[tid] = (e < nE) ? eidx[(size_t)nE + e] : 0;
    }
    for (int i = tid; i < 32 * 16; i += 256) {
        int r = i >> 4, c4 = (i & 15) << 2;
        float4 v = make_float4(0.f, 0.f, 0.f, 0.f);
        int e = tile0 + r;
        if (e < nE) v = *reinterpret_cast<const float4*>(ef + (size_t)e * DD + c4);
        shE2[r * 64 + c4 + 0] = make_float2(v.x, v.x);
        shE2[r * 64 + c4 + 1] = make_float2(v.y, v.y);
        shE2[r * 64 + c4 + 2] = make_float2(v.z, v.z);
        shE2[r * 64 + c4 + 3] = make_float2(v.w, v.w);
    }
    for (int i = tid; i < 64 * 16; i += 256)
        reinterpret_cast<float4*>(shW)[i] = reinterpret_cast<const float4*>(Weg)[i];
    __syncthreads();

    const int cg = tid & 15, rg = tid >> 4;
    const ull* shEu = reinterpret_cast<const ull*>(shE2);
    const ull* shWu = reinterpret_cast<const ull*>(shW);

    float4 bb = reinterpret_cast<const float4*>(beg)[cg];
    ull b01 = pk(bb.x, bb.y), b23 = pk(bb.z, bb.w);
    ull a01[2] = {b01, b01};
    ull a23[2] = {b23, b23};
    #pragma unroll 8
    for (int k = 0; k < 64; k++) {
        ull w01 = shWu[k * 32 + (cg << 1)];
        ull w23 = shWu[k * 32 + (cg << 1) + 1];
        ull e0 = shEu[(rg * 2 + 0) * 64 + k];
        ull e1 = shEu[(rg * 2 + 1) * 64 + k];
        a01[0] = fma2(e0, w01, a01[0]); a23[0] = fma2(e0, w23, a23[0]);
        a01[1] = fma2(e1, w01, a01[1]); a23[1] = fma2(e1, w23, a23[1]);
    }

    float lsum[4] = {0.f, 0.f, 0.f, 0.f};
    float lsq[4]  = {0.f, 0.f, 0.f, 0.f};
    #pragma unroll
    for (int rr = 0; rr < 2; rr++) {
        int li = rg * 2 + rr;
        int e = tile0 + li;
        if (e >= nE) continue;
        int s = shS[li], d = shD[li];
        float m0, m1, m2, m3;
        upk(a01[rr], m0, m1); upk(a23[rr], m2, m3);
        float4 es = *reinterpret_cast<const float4*>(g_esrc + (size_t)s * DD + (cg << 2));
        float4 ed = *reinterpret_cast<const float4*>(g_edst + (size_t)d * DD + (cg << 2));
        m0 += es.x + ed.x; m1 += es.y + ed.y;
        m2 += es.z + ed.z; m3 += es.w + ed.w;
        *reinterpret_cast<float4*>(g_m + (size_t)e * DD + (cg << 2)) =
            make_float4(m0, m1, m2, m3);
        float s0 = sigmoidf_(m0), s1 = sigmoidf_(m1);
        float s2 = sigmoidf_(m2), s3 = sigmoidf_(m3);
        float4 bh = *reinterpret_cast<const float4*>(g_Bh + (size_t)s * DD + (cg << 2));
        red4(g_num + (size_t)d * DD + (cg << 2), bh.x * s0, bh.y * s1, bh.z * s2, bh.w * s3);
        red4(g_den + (size_t)d * DD + (cg << 2), s0, s1, s2, s3);
        lsum[0] += m0; lsum[1] += m1; lsum[2] += m2; lsum[3] += m3;
        lsq[0] += m0 * m0; lsq[1] += m1 * m1; lsq[2] += m2 * m2; lsq[3] += m3 * m3;
    }

    // lanes l and l^16 share cg -> combine, then shared, then one red.v4/block
    #pragma unroll
    for (int j = 0; j < 4; j++) {
        lsum[j] += __shfl_xor_sync(0xffffffffu, lsum[j], 16);
        lsq[j]  += __shfl_xor_sync(0xffffffffu, lsq[j], 16);
    }
    if ((tid & 16) == 0) {
        #pragma unroll
        for (int j = 0; j < 4; j++) {
            atomicAdd(&shSum[(cg << 2) + j], lsum[j]);
            atomicAdd(&shSq [(cg << 2) + j], lsq[j]);
        }
    }
    __syncthreads();
    if (tid < 16) {
        int t4 = tid << 2;
        red4(&g_stats[t4], shSum[t4], shSum[t4 + 1], shSum[t4 + 2], shSum[t4 + 3]);
    } else if (tid < 32) {
        int t4 = (tid - 16) << 2;
        red4(&g_stats[64 + t4], shSq[t4], shSq[t4 + 1], shSq[t4 + 2], shSq[t4 + 3]);
    }
}

// ---------------- node pre-activation: grid-stride, register accumulation ---
__global__ __launch_bounds__(256) void node_pre(int nN)
{
    __shared__ float shSum[64], shSq[64];
    if (threadIdx.x < 64) { shSum[threadIdx.x] = 0.f; shSq[threadIdx.x] = 0.f; }
    __syncthreads();

    const int stride = gridDim.x * 256;
    const int tot = nN * 16;
    const int cg = threadIdx.x & 15;   // stride is a multiple of 16 -> cg constant
    float l0 = 0.f, l1 = 0.f, l2 = 0.f, l3 = 0.f;
    float q0 = 0.f, q1 = 0.f, q2 = 0.f, q3 = 0.f;
    for (int idx = blockIdx.x * 256 + threadIdx.x; idx < tot; idx += stride) {
        float4 xs = reinterpret_cast<const float4*>(g_xs)[idx];
        float4 nu = reinterpret_cast<const float4*>(g_num)[idx];
        float4 de = reinterpret_cast<const float4*>(g_den)[idx];
        float4 v;
        v.x = xs.x + nu.x / (de.x + 1e-6f);
        v.y = xs.y + nu.y / (de.y + 1e-6f);
        v.z = xs.z + nu.z / (de.z + 1e-6f);
        v.w = xs.w + nu.w / (de.w + 1e-6f);
        reinterpret_cast<float4*>(g_xpre)[idx] = v;
        l0 += v.x; l1 += v.y; l2 += v.z; l3 += v.w;
        q0 += v.x * v.x; q1 += v.y * v.y; q2 += v.z * v.z; q3 += v.w * v.w;
    }
    l0 += __shfl_xor_sync(0xffffffffu, l0, 16); q0 += __shfl_xor_sync(0xffffffffu, q0, 16);
    l1 += __shfl_xor_sync(0xffffffffu, l1, 16); q1 += __shfl_xor_sync(0xffffffffu, q1, 16);
    l2 += __shfl_xor_sync(0xffffffffu, l2, 16); q2 += __shfl_xor_sync(0xffffffffu, q2, 16);
    l3 += __shfl_xor_sync(0xffffffffu, l3, 16); q3 += __shfl_xor_sync(0xffffffffu, q3, 16);
    if ((threadIdx.x & 16) == 0) {
        atomicAdd(&shSum[(cg << 2) + 0], l0); atomicAdd(&shSum[(cg << 2) + 1], l1);
        atomicAdd(&shSum[(cg << 2) + 2], l2); atomicAdd(&shSum[(cg << 2) + 3], l3);
        atomicAdd(&shSq [(cg << 2) + 0], q0); atomicAdd(&shSq [(cg << 2) + 1], q1);
        atomicAdd(&shSq [(cg << 2) + 2], q2); atomicAdd(&shSq [(cg << 2) + 3], q3);
    }
    __syncthreads();
    if (threadIdx.x < 16) {
        int t4 = threadIdx.x << 2;
        red4(&g_stats[128 + t4], shSum[t4], shSum[t4 + 1], shSum[t4 + 2], shSum[t4 + 3]);
    } else if (threadIdx.x < 32) {
        int t4 = (threadIdx.x - 16) << 2;
        red4(&g_stats[192 + t4], shSq[t4], shSq[t4 + 1], shSq[t4 + 2], shSq[t4 + 3]);
    }
}

// ---------------- finalize BN stats -> scale/shift ---------------------------
__global__ void finalize_stats(const float* __restrict__ gn, const float* __restrict__ btn,
                               const float* __restrict__ ge, const float* __restrict__ bte,
                               int nN, int nE)
{
    int t = threadIdx.x;
    if (t >= 64) return;
    float invE = 1.f / (float)nE;
    float me = g_stats[t] * invE;
    float ve = g_stats[64 + t] * invE - me * me;
    float sce = rsqrtf(ve + 1e-5f) * ge[t];
    g_stats[256 + t] = sce;
    g_stats[320 + t] = bte[t] - me * sce;

    float invN = 1.f / (float)nN;
    float mn = g_stats[128 + t] * invN;
    float vn = g_stats[192 + t] * invN - mn * mn;
    float scn = rsqrtf(vn + 1e-5f) * gn[t];
    g_stats[384 + t] = scn;
    g_stats[448 + t] = btn[t] - mn * scn;
}

// ---------------- merged outputs ---------------------------------------------
__global__ __launch_bounds__(256) void outputs_k(const float* __restrict__ nf,
                                                 const float* __restrict__ ef,
                                                 float* __restrict__ outx,
                                                 float* __restrict__ outy,
                                                 int nN, int nE)
{
    int idx = blockIdx.x * 256 + threadIdx.x;
    int nTot = nN * 16;
    if (idx < nTot) {
        int cg = idx & 15;
        float4 sc = *reinterpret_cast<const float4*>(&g_stats[384 + (cg << 2)]);
        float4 sh = *reinterpret_cast<const float4*>(&g_stats[448 + (cg << 2)]);
        float4 xp = reinterpret_cast<const float4*>(g_xpre)[idx];
        float4 nv = reinterpret_cast<const float4*>(nf)[idx];
        float t0 = xp.x * sc.x + sh.x;
        float t1 = xp.y * sc.y + sh.y;
        float t2 = xp.z * sc.z + sh.z;
        float t3 = xp.w * sc.w + sh.w;
        float4 o;
        o.x = nv.x + t0 * sigmoidf_(t0);
        o.y = nv.y + t1 * sigmoidf_(t1);
        o.z = nv.z + t2 * sigmoidf_(t2);
        o.w = nv.w + t3 * sigmoidf_(t3);
        reinterpret_cast<float4*>(outx)[idx] = o;
    } else {
        int j = idx - nTot;
        if (j >= nE * 16) return;
        int cg = j & 15;
        float4 sc = *reinterpret_cast<const float4*>(&g_stats[256 + (cg << 2)]);
        float4 sh = *reinterpret_cast<const float4*>(&g_stats[320 + (cg << 2)]);
        float4 mv = reinterpret_cast<const float4*>(g_m)[j];
        float4 ev = reinterpret_cast<const float4*>(ef)[j];
        float t0 = mv.x * sc.x + sh.x;
        float t1 = mv.y * sc.y + sh.y;
        float t2 = mv.z * sc.z + sh.z;
        float t3 = mv.w * sc.w + sh.w;
        float4 o;
        o.x = ev.x + t0 * sigmoidf_(t0);
        o.y = ev.y + t1 * sigmoidf_(t1);
        o.z = ev.z + t2 * sigmoidf_(t2);
        o.w = ev.w + t3 * sigmoidf_(t3);
        reinterpret_cast<float4*>(outy)[j] = o;
    }
}

// ---------------- launch -----------------------------------------------------
extern "C" void kernel_launch(void* const* d_in, const int* in_sizes, int n_in,
                              void* d_out, int out_size)
{
    (void)n_in; (void)out_size;
    const int* eidx  = (const int*)d_in[0];   // edge_index is int32 (JAX x64 disabled)
    const float* nf  = (const float*)d_in[1];
    const float* ef  = (const float*)d_in[2];
    const float* Wsg = (const float*)d_in[3];  const float* bsg = (const float*)d_in[4];
    const float* Wdg = (const float*)d_in[5];  const float* bdg = (const float*)d_in[6];
    const float* Weg = (const float*)d_in[7];  const float* beg = (const float*)d_in[8];
    const float* Wsu = (const float*)d_in[9];  const float* bsu = (const float*)d_in[10];
    const float* Wdu = (const float*)d_in[11]; const float* bdu = (const float*)d_in[12];
    const float* gmn = (const float*)d_in[13]; const float* btn = (const float*)d_in[14];
    const float* gme = (const float*)d_in[15]; const float* bte = (const float*)d_in[16];

    int nE = in_sizes[0] / 2;
    int nN = in_sizes[1] / DD;

    float* outx = (float*)d_out;
    float* outy = outx + (size_t)nN * DD;

    node_gemm4<<<(nN + 63) / 64, 256>>>(nf, Wsg, bsg, Wdg, bdg, Wsu, bsu, Wdu, bdu, nN);
    edge_pass1<<<(nE + 31) / 32, 256>>>(ef, eidx, Weg, beg, nE);
    node_pre<<<391, 256>>>(nN);
    finalize_stats<<<1, 64>>>(gmn, btn, gme, bte, nN, nE);
    outputs_k<<<((nN + nE) * 16 + 255) / 256, 256>>>(nf, ef, outx, outy, nN, nE);
}

// round 4
// speedup vs baseline: 1.3445x; 1.3445x over previous
#include <cuda_runtime.h>

#define DD 64
#define MAXN 50000
#define MAXE 800000

// ---------------- scratch (device globals: no allocation allowed) ----------
__device__ __align__(16) float g_esrc[(size_t)MAXN * DD];
__device__ __align__(16) float g_edst[(size_t)MAXN * DD];
__device__ __align__(16) float g_Bh  [(size_t)MAXN * DD];
__device__ __align__(16) float g_xs  [(size_t)MAXN * DD];
__device__ __align__(16) float g_xpre[(size_t)MAXN * DD];
__device__ __align__(16) float g_num [(size_t)MAXN * DD];
__device__ __align__(16) float g_den [(size_t)MAXN * DD];
__device__ __align__(16) float g_m   [(size_t)MAXE * DD];
// [0:64) edge_sum [64:128) edge_sumsq [128:192) node_sum [192:256) node_sumsq
// [256:320) edge_scale [320:384) edge_shift [384:448) node_scale [448:512) node_shift
__device__ __align__(16) float g_stats[512];

__device__ __forceinline__ float sigmoidf_(float x) {
    return __fdividef(1.0f, 1.0f + __expf(-x));
}
// vector reduction: 4 fp32 adds in one L2 op (sm_90+)
__device__ __forceinline__ void red4(float* p, float a, float b, float c, float d) {
    asm volatile("{\n\t.reg .u64 q;\n\tcvta.to.global.u64 q, %0;\n\t"
                 "red.global.add.v4.f32 [q], {%1, %2, %3, %4};\n\t}"
                 :: "l"(p), "f"(a), "f"(b), "f"(c), "f"(d) : "memory");
}

// ---------------- node-side 4 GEMMs (N x 64 @ 64 x 64) ----------------------
// tile: 64 rows, 256 threads, each thread 4 rows x 4 cols (R2-proven kernel)
__global__ __launch_bounds__(256) void node_gemm4(
    const float* __restrict__ nf,
    const float* __restrict__ Wsg, const float* __restrict__ bsg,
    const float* __restrict__ Wdg, const float* __restrict__ bdg,
    const float* __restrict__ Wsu, const float* __restrict__ bsu,
    const float* __restrict__ Wdu, const float* __restrict__ bdu,
    int n)
{
    __shared__ float shIn[64 * 65];
    __shared__ float shW[64 * 64];
    const int tid = threadIdx.x;
    const int tile0 = blockIdx.x * 64;

    for (int i = tid; i < 64 * 16; i += 256) {
        int r = i >> 4, c4 = (i & 15) << 2;
        float4 v = make_float4(0.f, 0.f, 0.f, 0.f);
        int row = tile0 + r;
        if (row < n) v = *reinterpret_cast<const float4*>(nf + (size_t)row * DD + c4);
        shIn[r * 65 + c4 + 0] = v.x; shIn[r * 65 + c4 + 1] = v.y;
        shIn[r * 65 + c4 + 2] = v.z; shIn[r * 65 + c4 + 3] = v.w;
    }

    const float* Ws[4] = {Wsg, Wdg, Wsu, Wdu};
    const float* bs[4] = {bsg, bdg, bsu, bdu};
    float* outs[4] = {g_esrc, g_edst, g_xs, g_Bh};

    const int cg = tid & 15, rg = tid >> 4;

    #pragma unroll
    for (int p = 0; p < 4; ++p) {
        __syncthreads();
        for (int i = tid; i < 64 * 16; i += 256)
            reinterpret_cast<float4*>(shW)[i] = reinterpret_cast<const float4*>(Ws[p])[i];
        __syncthreads();

        float4 bb = reinterpret_cast<const float4*>(bs[p])[cg];
        float acc[4][4];
        #pragma unroll
        for (int r = 0; r < 4; r++) {
            acc[r][0] = bb.x; acc[r][1] = bb.y; acc[r][2] = bb.z; acc[r][3] = bb.w;
        }
        #pragma unroll 8
        for (int k = 0; k < 64; k++) {
            float4 w = *reinterpret_cast<const float4*>(&shW[k * 64 + (cg << 2)]);
            #pragma unroll
            for (int r = 0; r < 4; r++) {
                float ev = shIn[(rg * 4 + r) * 65 + k];
                acc[r][0] += ev * w.x; acc[r][1] += ev * w.y;
                acc[r][2] += ev * w.z; acc[r][3] += ev * w.w;
            }
        }
        float* op = outs[p];
        #pragma unroll
        for (int r = 0; r < 4; r++) {
            int row = tile0 + rg * 4 + r;
            if (row < n) {
                *reinterpret_cast<float4*>(op + (size_t)row * DD + (cg << 2)) =
                    make_float4(acc[r][0], acc[r][1], acc[r][2], acc[r][3]);
            }
        }
    }

    // fused zeroing of num/den for this row tile + stats (block 0)
    float4 z = make_float4(0.f, 0.f, 0.f, 0.f);
    for (int i = tid; i < 64 * 16; i += 256) {
        int r = i >> 4, c4 = (i & 15) << 2;
        int row = tile0 + r;
        if (row < n) {
            *reinterpret_cast<float4*>(g_num + (size_t)row * DD + c4) = z;
            *reinterpret_cast<float4*>(g_den + (size_t)row * DD + c4) = z;
        }
    }
    if (blockIdx.x == 0) g_stats[tid] = 0.f;   // zero sums [0:256)
}

// ---------------- edge pass 1: GEMM + gather + sigma + red.v4 scatter -------
// 64 edges/block, 256 threads (R2-proven GEMM core; scatter via red.v4)
__global__ __launch_bounds__(256) void edge_pass1(
    const float* __restrict__ ef, const int* __restrict__ eidx,
    const float* __restrict__ Weg, const float* __restrict__ beg,
    int nE)
{
    __shared__ float shEf[64 * 65];
    __shared__ float shW[64 * 64];
    __shared__ int shS[64], shD[64];
    __shared__ float shSum[64], shSq[64];

    const int tid = threadIdx.x;
    const int tile0 = blockIdx.x * 64;

    if (tid < 64) {
        shSum[tid] = 0.f; shSq[tid] = 0.f;
        int e = tile0 + tid;
        if (e < nE) { shS[tid] = eidx[e]; shD[tid] = eidx[(size_t)nE + e]; }
        else        { shS[tid] = 0;       shD[tid] = 0; }
    }
    for (int i = tid; i < 64 * 16; i += 256) {
        int r = i >> 4, c4 = (i & 15) << 2;
        float4 v = make_float4(0.f, 0.f, 0.f, 0.f);
        int e = tile0 + r;
        if (e < nE) v = *reinterpret_cast<const float4*>(ef + (size_t)e * DD + c4);
        shEf[r * 65 + c4 + 0] = v.x; shEf[r * 65 + c4 + 1] = v.y;
        shEf[r * 65 + c4 + 2] = v.z; shEf[r * 65 + c4 + 3] = v.w;
    }
    for (int i = tid; i < 64 * 16; i += 256)
        reinterpret_cast<float4*>(shW)[i] = reinterpret_cast<const float4*>(Weg)[i];
    __syncthreads();

    const int cg = tid & 15, rg = tid >> 4;
    float4 bb = reinterpret_cast<const float4*>(beg)[cg];
    float acc[4][4];
    #pragma unroll
    for (int r = 0; r < 4; r++) {
        acc[r][0] = bb.x; acc[r][1] = bb.y; acc[r][2] = bb.z; acc[r][3] = bb.w;
    }
    #pragma unroll 8
    for (int k = 0; k < 64; k++) {
        float4 w = *reinterpret_cast<const float4*>(&shW[k * 64 + (cg << 2)]);
        #pragma unroll
        for (int r = 0; r < 4; r++) {
            float ev = shEf[(rg * 4 + r) * 65 + k];
            acc[r][0] += ev * w.x; acc[r][1] += ev * w.y;
            acc[r][2] += ev * w.z; acc[r][3] += ev * w.w;
        }
    }

    float lsum[4] = {0.f, 0.f, 0.f, 0.f};
    float lsq[4]  = {0.f, 0.f, 0.f, 0.f};
    #pragma unroll
    for (int r = 0; r < 4; r++) {
        int li = rg * 4 + r;
        int e = tile0 + li;
        if (e >= nE) continue;
        int s = shS[li], d = shD[li];
        float4 es = *reinterpret_cast<const float4*>(g_esrc + (size_t)s * DD + (cg << 2));
        float4 ed = *reinterpret_cast<const float4*>(g_edst + (size_t)d * DD + (cg << 2));
        float m0 = acc[r][0] + es.x + ed.x;
        float m1 = acc[r][1] + es.y + ed.y;
        float m2 = acc[r][2] + es.z + ed.z;
        float m3 = acc[r][3] + es.w + ed.w;
        *reinterpret_cast<float4*>(g_m + (size_t)e * DD + (cg << 2)) =
            make_float4(m0, m1, m2, m3);
        float s0 = sigmoidf_(m0), s1 = sigmoidf_(m1);
        float s2 = sigmoidf_(m2), s3 = sigmoidf_(m3);
        float4 bh = *reinterpret_cast<const float4*>(g_Bh + (size_t)s * DD + (cg << 2));
        red4(g_num + (size_t)d * DD + (cg << 2), bh.x * s0, bh.y * s1, bh.z * s2, bh.w * s3);
        red4(g_den + (size_t)d * DD + (cg << 2), s0, s1, s2, s3);
        lsum[0] += m0; lsum[1] += m1; lsum[2] += m2; lsum[3] += m3;
        lsq[0] += m0 * m0; lsq[1] += m1 * m1; lsq[2] += m2 * m2; lsq[3] += m3 * m3;
    }

    // lanes l and l^16 share cg -> combine, then shared, then one red.v4/block
    #pragma unroll
    for (int j = 0; j < 4; j++) {
        lsum[j] += __shfl_xor_sync(0xffffffffu, lsum[j], 16);
        lsq[j]  += __shfl_xor_sync(0xffffffffu, lsq[j], 16);
    }
    if ((tid & 16) == 0) {
        #pragma unroll
        for (int j = 0; j < 4; j++) {
            atomicAdd(&shSum[(cg << 2) + j], lsum[j]);
            atomicAdd(&shSq [(cg << 2) + j], lsq[j]);
        }
    }
    __syncthreads();
    if (tid < 16) {
        int t4 = tid << 2;
        red4(&g_stats[t4], shSum[t4], shSum[t4 + 1], shSum[t4 + 2], shSum[t4 + 3]);
    } else if (tid < 32) {
        int t4 = (tid - 16) << 2;
        red4(&g_stats[64 + t4], shSq[t4], shSq[t4 + 1], shSq[t4 + 2], shSq[t4 + 3]);
    }
}

// ---------------- node pre-activation: grid-stride, register accumulation ---
__global__ __launch_bounds__(256) void node_pre(int nN)
{
    __shared__ float shSum[64], shSq[64];
    if (threadIdx.x < 64) { shSum[threadIdx.x] = 0.f; shSq[threadIdx.x] = 0.f; }
    __syncthreads();

    const int stride = gridDim.x * 256;
    const int tot = nN * 16;
    const int cg = threadIdx.x & 15;   // stride is a multiple of 16 -> cg constant
    float l0 = 0.f, l1 = 0.f, l2 = 0.f, l3 = 0.f;
    float q0 = 0.f, q1 = 0.f, q2 = 0.f, q3 = 0.f;
    for (int idx = blockIdx.x * 256 + threadIdx.x; idx < tot; idx += stride) {
        float4 xs = reinterpret_cast<const float4*>(g_xs)[idx];
        float4 nu = reinterpret_cast<const float4*>(g_num)[idx];
        float4 de = reinterpret_cast<const float4*>(g_den)[idx];
        float4 v;
        v.x = xs.x + nu.x / (de.x + 1e-6f);
        v.y = xs.y + nu.y / (de.y + 1e-6f);
        v.z = xs.z + nu.z / (de.z + 1e-6f);
        v.w = xs.w + nu.w / (de.w + 1e-6f);
        reinterpret_cast<float4*>(g_xpre)[idx] = v;
        l0 += v.x; l1 += v.y; l2 += v.z; l3 += v.w;
        q0 += v.x * v.x; q1 += v.y * v.y; q2 += v.z * v.z; q3 += v.w * v.w;
    }
    l0 += __shfl_xor_sync(0xffffffffu, l0, 16); q0 += __shfl_xor_sync(0xffffffffu, q0, 16);
    l1 += __shfl_xor_sync(0xffffffffu, l1, 16); q1 += __shfl_xor_sync(0xffffffffu, q1, 16);
    l2 += __shfl_xor_sync(0xffffffffu, l2, 16); q2 += __shfl_xor_sync(0xffffffffu, q2, 16);
    l3 += __shfl_xor_sync(0xffffffffu, l3, 16); q3 += __shfl_xor_sync(0xffffffffu, q3, 16);
    if ((threadIdx.x & 16) == 0) {
        atomicAdd(&shSum[(cg << 2) + 0], l0); atomicAdd(&shSum[(cg << 2) + 1], l1);
        atomicAdd(&shSum[(cg << 2) + 2], l2); atomicAdd(&shSum[(cg << 2) + 3], l3);
        atomicAdd(&shSq [(cg << 2) + 0], q0); atomicAdd(&shSq [(cg << 2) + 1], q1);
        atomicAdd(&shSq [(cg << 2) + 2], q2); atomicAdd(&shSq [(cg << 2) + 3], q3);
    }
    __syncthreads();
    if (threadIdx.x < 16) {
        int t4 = threadIdx.x << 2;
        red4(&g_stats[128 + t4], shSum[t4], shSum[t4 + 1], shSum[t4 + 2], shSum[t4 + 3]);
    } else if (threadIdx.x < 32) {
        int t4 = (threadIdx.x - 16) << 2;
        red4(&g_stats[192 + t4], shSq[t4], shSq[t4 + 1], shSq[t4 + 2], shSq[t4 + 3]);
    }
}

// ---------------- finalize BN stats -> scale/shift ---------------------------
__global__ void finalize_stats(const float* __restrict__ gn, const float* __restrict__ btn,
                               const float* __restrict__ ge, const float* __restrict__ bte,
                               int nN, int nE)
{
    int t = threadIdx.x;
    if (t >= 64) return;
    float invE = 1.f / (float)nE;
    float me = g_stats[t] * invE;
    float ve = g_stats[64 + t] * invE - me * me;
    float sce = rsqrtf(ve + 1e-5f) * ge[t];
    g_stats[256 + t] = sce;
    g_stats[320 + t] = bte[t] - me * sce;

    float invN = 1.f / (float)nN;
    float mn = g_stats[128 + t] * invN;
    float vn = g_stats[192 + t] * invN - mn * mn;
    float scn = rsqrtf(vn + 1e-5f) * gn[t];
    g_stats[384 + t] = scn;
    g_stats[448 + t] = btn[t] - mn * scn;
}

// ---------------- merged outputs ---------------------------------------------
__global__ __launch_bounds__(256) void outputs_k(const float* __restrict__ nf,
                                                 const float* __restrict__ ef,
                                                 float* __restrict__ outx,
                                                 float* __restrict__ outy,
                                                 int nN, int nE)
{
    int idx = blockIdx.x * 256 + threadIdx.x;
    int nTot = nN * 16;
    if (idx < nTot) {
        int cg = idx & 15;
        float4 sc = *reinterpret_cast<const float4*>(&g_stats[384 + (cg << 2)]);
        float4 sh = *reinterpret_cast<const float4*>(&g_stats[448 + (cg << 2)]);
        float4 xp = reinterpret_cast<const float4*>(g_xpre)[idx];
        float4 nv = reinterpret_cast<const float4*>(nf)[idx];
        float t0 = xp.x * sc.x + sh.x;
        float t1 = xp.y * sc.y + sh.y;
        float t2 = xp.z * sc.z + sh.z;
        float t3 = xp.w * sc.w + sh.w;
        float4 o;
        o.x = nv.x + t0 * sigmoidf_(t0);
        o.y = nv.y + t1 * sigmoidf_(t1);
        o.z = nv.z + t2 * sigmoidf_(t2);
        o.w = nv.w + t3 * sigmoidf_(t3);
        reinterpret_cast<float4*>(outx)[idx] = o;
    } else {
        int j = idx - nTot;
        if (j >= nE * 16) return;
        int cg = j & 15;
        float4 sc = *reinterpret_cast<const float4*>(&g_stats[256 + (cg << 2)]);
        float4 sh = *reinterpret_cast<const float4*>(&g_stats[320 + (cg << 2)]);
        float4 mv = reinterpret_cast<const float4*>(g_m)[j];
        float4 ev = reinterpret_cast<const float4*>(ef)[j];
        float t0 = mv.x * sc.x + sh.x;
        float t1 = mv.y * sc.y + sh.y;
        float t2 = mv.z * sc.z + sh.z;
        float t3 = mv.w * sc.w + sh.w;
        float4 o;
        o.x = ev.x + t0 * sigmoidf_(t0);
        o.y = ev.y + t1 * sigmoidf_(t1);
        o.z = ev.z + t2 * sigmoidf_(t2);
        o.w = ev.w + t3 * sigmoidf_(t3);
        reinterpret_cast<float4*>(outy)[j] = o;
    }
}

// ---------------- launch -----------------------------------------------------
extern "C" void kernel_launch(void* const* d_in, const int* in_sizes, int n_in,
                              void* d_out, int out_size)
{
    (void)n_in; (void)out_size;
    const int* eidx  = (const int*)d_in[0];   // edge_index is int32 (JAX x64 disabled)
    const float* nf  = (const float*)d_in[1];
    const float* ef  = (const float*)d_in[2];
    const float* Wsg = (const float*)d_in[3];  const float* bsg = (const float*)d_in[4];
    const float* Wdg = (const float*)d_in[5];  const float* bdg = (const float*)d_in[6];
    const float* Weg = (const float*)d_in[7];  const float* beg = (const float*)d_in[8];
    const float* Wsu = (const float*)d_in[9];  const float* bsu = (const float*)d_in[10];
    const float* Wdu = (const float*)d_in[11]; const float* bdu = (const float*)d_in[12];
    const float* gmn = (const float*)d_in[13]; const float* btn = (const float*)d_in[14];
    const float* gme = (const float*)d_in[15]; const float* bte = (const float*)d_in[16];

    int nE = in_sizes[0] / 2;
    int nN = in_sizes[1] / DD;

    float* outx = (float*)d_out;
    float* outy = outx + (size_t)nN * DD;

    node_gemm4<<<(nN + 63) / 64, 256>>>(nf, Wsg, bsg, Wdg, bdg, Wsu, bsu, Wdu, bdu, nN);
    edge_pass1<<<(nE + 63) / 64, 256>>>(ef, eidx, Weg, beg, nE);
    node_pre<<<391, 256>>>(nN);
    finalize_stats<<<1, 64>>>(gmn, btn, gme, bte, nN, nE);
    outputs_k<<<((nN + nE) * 16 + 255) / 256, 256>>>(nf, ef, outx, outy, nN, nE);
}